// round 15
// baseline (speedup 1.0000x reference)
#include <cuda_runtime.h>
#include <cuda_bf16.h>

// Problem constants
#define NTOK 16384      // B*H*W
#define KC   8192
#define DD   256
#define IMG  262144     // C*H*W
#define HW   1024

#define OUT_LOSS 4194304
#define OUT_ENC  4194305

// GEMM tiling: M = codes, N = tokens (round-12 validated)
#define CTM 128
#define CTN 256
#define CK  32
#define NCH (DD / CK)   // 8
#define NSTG 4
#define A_STG 8192
#define B_STG 16384
#define B_BASE (NSTG * A_STG)                 // 32768
#define GEMM_SMEM (B_BASE + NSTG * B_STG)     // 98304

// u8 distance quantization: dq = round((d + 0.032) * 4000), step 2.5e-4
#define DQ_BIAS  128.0f     // = 0.032 * 4000
#define DQ_SCALE 4000.0f
#define TQ_WIN   6          // collect window in steps (1.5e-3)
#define CAND_CAP 64

typedef unsigned int u32;

// -------- scratch (device globals; no allocation allowed) --------
__device__ float g_cnorm[KC];
__device__ float g_xnorm[NTOK];
__device__ int   g_idx[NTOK];
__device__ float g_partial[256];
__device__ u32   g_dmin[NTOK];                              // u8-domain min (0..255)
__device__ int   g_ccnt[NTOK];
__device__ int   g_cand[NTOK * CAND_CAP];
__device__ __align__(16) __nv_bfloat16 g_xb[NTOK * DD];     // x [b][d][hw] bf16
__device__ __align__(16) __nv_bfloat16 g_cbb[KC * DD];      // [code][d] bf16
__device__ __align__(16) unsigned char g_dq[134217728];     // [code][token] u8, 128MB

// -------- helpers --------
__device__ __forceinline__ u32 smem_u32(const void* p) {
    u32 a;
    asm("{ .reg .u64 t; cvta.to.shared.u64 t, %1; cvt.u32.u64 %0, t; }" : "=r"(a) : "l"(p));
    return a;
}
__device__ __forceinline__ void cpa(u32 dst, const void* src) {
    asm volatile("cp.async.cg.shared.global [%0], [%1], 16;" :: "r"(dst), "l"(src) : "memory");
}
#define CPC() asm volatile("cp.async.commit_group;" ::: "memory")
#define CPW(n) asm volatile("cp.async.wait_group %0;" :: "n"(n) : "memory")
__device__ __forceinline__ void ldsm4(u32& r0, u32& r1, u32& r2, u32& r3, u32 a) {
    asm volatile("ldmatrix.sync.aligned.m8n8.x4.shared.b16 {%0,%1,%2,%3}, [%4];"
                 : "=r"(r0), "=r"(r1), "=r"(r2), "=r"(r3) : "r"(a));
}
__device__ __forceinline__ void ldsm4t(u32& r0, u32& r1, u32& r2, u32& r3, u32 a) {
    asm volatile("ldmatrix.sync.aligned.m8n8.x4.trans.shared.b16 {%0,%1,%2,%3}, [%4];"
                 : "=r"(r0), "=r"(r1), "=r"(r2), "=r"(r3) : "r"(a));
}
__device__ __forceinline__ void mma16816(float* c, const u32* a, u32 b0, u32 b1) {
    asm volatile("mma.sync.aligned.m16n8k16.row.col.f32.bf16.bf16.f32 "
                 "{%0,%1,%2,%3}, {%4,%5,%6,%7}, {%8,%9}, {%0,%1,%2,%3};"
                 : "+f"(c[0]), "+f"(c[1]), "+f"(c[2]), "+f"(c[3])
                 : "r"(a[0]), "r"(a[1]), "r"(a[2]), "r"(a[3]), "r"(b0), "r"(b1));
}
__device__ __forceinline__ u32 pack_bf(float lo, float hi) {  // lo -> bits[0:16)
    u32 r;
    asm("cvt.rn.bf16x2.f32 %0, %1, %2;" : "=r"(r) : "f"(hi), "f"(lo));
    return r;
}
__device__ __forceinline__ int quant8(float d) {
    int q = __float2int_rn(fmaf(d, DQ_SCALE, DQ_BIAS));
    return max(0, min(255, q));
}

// ============================================================
// Kernel 1: FUSED norms (strict sequential fp32 chains, bit-exact)
// + bf16 conversion. Blocks [0,96): norms+init; [96,3168): convert.
// ============================================================
__global__ __launch_bounds__(256) void pre_kernel(const float* __restrict__ x,
                                                  const float* __restrict__ cb) {
    int blk = blockIdx.x;
    if (blk < 32) {
        int k = blk * 256 + threadIdx.x;
        const float* p = cb + (size_t)k * DD;
        float s = 0.f;
#pragma unroll 8
        for (int d = 0; d < DD; ++d) { float v = p[d]; s = __fadd_rn(s, __fmul_rn(v, v)); }
        g_cnorm[k] = s;
    } else if (blk < 96) {
        int n  = (blk - 32) * 256 + threadIdx.x;
        int b  = n >> 10, hw = n & (HW - 1);
        const float* p = x + (size_t)b * IMG + hw;
        float s = 0.f;
#pragma unroll 8
        for (int d = 0; d < DD; ++d) { float v = p[(size_t)d * HW]; s = __fadd_rn(s, __fmul_rn(v, v)); }
        g_xnorm[n] = s;
        g_dmin[n]  = 255u;
        g_ccnt[n]  = 0;
    } else {
        size_t i = ((size_t)(blk - 96) * 256 + threadIdx.x) * 8;
        const float4* s;
        __nv_bfloat16* d;
        if (i < (size_t)NTOK * DD) { s = (const float4*)(x + i);              d = g_xb + i; }
        else { size_t j = i - (size_t)NTOK * DD; s = (const float4*)(cb + j); d = g_cbb + j; }
        float4 v0 = s[0], v1 = s[1];
        uint4 w;
        w.x = pack_bf(v0.x, v0.y); w.y = pack_bf(v0.z, v0.w);
        w.z = pack_bf(v1.x, v1.y); w.w = pack_bf(v1.z, v1.w);
        *(uint4*)d = w;
    }
}

// ============================================================
// Kernel 2: HMMA bf16 prescreen GEMM (round-12 validated mainloop:
// 4-stage cp.async, empty-commit tail). Epilogue NOW stores u8
// quantized distances (half the bytes) + integer per-token min.
// ============================================================
__global__ __launch_bounds__(512, 1) void gemm_kernel() {
    extern __shared__ __align__(16) char sm[];
    const u32 smU = smem_u32(sm);
    const int tid  = threadIdx.x;
    const int lane = tid & 31;
    const int wid  = tid >> 5;
    const int wm   = wid & 3;      // code group (32 codes)
    const int wn   = wid >> 2;     // token group (64 tokens)

    const int code0 = (blockIdx.x & 63) * CTM;
    const int tok0  = (blockIdx.x >> 6) * CTN;
    const int bimg  = tok0 >> 10;
    const int hw0   = tok0 & (HW - 1);

    const int arow = tid >> 2, ac = tid & 3;
    const __nv_bfloat16* aG = g_cbb + (size_t)(code0 + arow) * DD + ac * 8;
    const u32 aOff = (u32)arow * 64u + (u32)((ac ^ ((arow >> 1) & 3))) * 16u;
    const int bd = tid >> 4, bc = tid & 15;
    const __nv_bfloat16* bG = g_xb + (size_t)bimg * IMG + hw0 + (size_t)bd * HW + bc * 8;
    const u32 bOff0 = (u32)bd * 512u + (u32)((bc        ^ (bd & 7))) * 16u;
    const u32 bOff1 = (u32)bd * 512u + (u32)(((bc + 16) ^ (bd & 7))) * 16u;

    float acc[2][8][4];
#pragma unroll
    for (int mi = 0; mi < 2; ++mi)
#pragma unroll
        for (int nt = 0; nt < 8; ++nt)
#pragma unroll
            for (int q = 0; q < 4; ++q) acc[mi][nt][q] = 0.f;

#define LOAD_CHUNK(ch) do {                                                   \
        const u32 _st = (u32)((ch) & (NSTG - 1));                             \
        cpa(smU + _st * A_STG + aOff, aG + (ch) * CK);                        \
        cpa(smU + B_BASE + _st * B_STG + bOff0, bG + (size_t)(ch) * CK * HW); \
        cpa(smU + B_BASE + _st * B_STG + bOff1,                               \
            bG + (size_t)(ch) * CK * HW + 128);                               \
        CPC();                                                                \
    } while (0)

    LOAD_CHUNK(0);
    LOAD_CHUNK(1);
    LOAD_CHUNK(2);

    const int sa = ((lane & 15) >> 1) & 3;
    const int sb = lane & 7;
    const u32 aFragBase = smU + (u32)(wm * 32 + (lane & 15)) * 64u;
    const u32 bFragBase = smU + B_BASE + (u32)(lane & 15) * 512u;

    for (int ch = 0; ch < NCH; ++ch) {
        CPW(2);                    // per-iter commits: chunks 0..ch landed
        __syncthreads();           // stage (ch-1)&3 readers all done
        if (ch + 3 < NCH) LOAD_CHUNK(ch + 3);
        else              CPC();   // EMPTY group keeps wait_group advancing

        const u32 st = (u32)(ch & (NSTG - 1));
#pragma unroll
        for (int kk = 0; kk < 2; ++kk) {
            u32 a0[4], a1[4];
            const u32 aTop = (u32)(((kk * 2 + (lane >> 4)) ^ sa)) * 16u + st * A_STG;
            ldsm4(a0[0], a0[1], a0[2], a0[3], aFragBase + aTop);
            ldsm4(a1[0], a1[1], a1[2], a1[3], aFragBase + 1024u + aTop);
            const u32 bRow = st * B_STG + (u32)(kk * 16) * 512u;
#pragma unroll
            for (int np = 0; np < 4; ++np) {
                u32 b0, b1, b2, b3;
                const u32 c = (u32)(((wn * 8 + np * 2 + (lane >> 4)) ^ sb)) * 16u;
                ldsm4t(b0, b1, b2, b3, bFragBase + bRow + c);
                mma16816(acc[0][2 * np],     a0, b0, b1);
                mma16816(acc[0][2 * np + 1], a0, b2, b3);
                mma16816(acc[1][2 * np],     a1, b0, b1);
                mma16816(acc[1][2 * np + 1], a1, b2, b3);
            }
        }
    }
#undef LOAD_CHUNK

    // ---- epilogue: u8 quantized store + integer per-token min ----
    int tmn[8][2];
#pragma unroll
    for (int nt = 0; nt < 8; ++nt) { tmn[nt][0] = 255; tmn[nt][1] = 255; }
#pragma unroll
    for (int mi = 0; mi < 2; ++mi)
#pragma unroll
        for (int h = 0; h < 2; ++h) {
            const int code = code0 + wm * 32 + mi * 16 + (lane >> 2) + h * 8;
            const float cn = g_cnorm[code];
            unsigned char* dst = g_dq + (size_t)code * NTOK + tok0 + wn * 64 + 2 * (lane & 3);
#pragma unroll
            for (int nt = 0; nt < 8; ++nt) {
                int q0 = quant8(fmaf(-2.f, acc[mi][nt][h * 2 + 0], cn));
                int q1 = quant8(fmaf(-2.f, acc[mi][nt][h * 2 + 1], cn));
                *(unsigned short*)(dst + nt * 8) = (unsigned short)(q0 | (q1 << 8));
                tmn[nt][0] = min(tmn[nt][0], q0);
                tmn[nt][1] = min(tmn[nt][1], q1);
            }
        }
#pragma unroll
    for (int nt = 0; nt < 8; ++nt)
#pragma unroll
        for (int off = 16; off >= 4; off >>= 1) {
            tmn[nt][0] = min(tmn[nt][0], __shfl_xor_sync(0xffffffffu, tmn[nt][0], off));
            tmn[nt][1] = min(tmn[nt][1], __shfl_xor_sync(0xffffffffu, tmn[nt][1], off));
        }
    if (lane < 4) {
#pragma unroll
        for (int nt = 0; nt < 8; ++nt) {
            int t = tok0 + wn * 64 + nt * 8 + 2 * lane;
            atomicMin(&g_dmin[t],     (u32)tmn[nt][0]);
            atomicMin(&g_dmin[t + 1], (u32)tmn[nt][1]);
        }
    }
}

// ============================================================
// Kernel 3: candidate collection — u8 rows, SIMD vcmpleu4.
// grid 1024 = 8 token-blocks(2048 tokens) x 128 code-slices(64).
// Thread owns 8 tokens (one 8B load per code row, coalesced).
// Exact integer window: dq <= dqmin + TQ_WIN.
// ============================================================
__global__ __launch_bounds__(256) void collect_kernel() {
    const int tok = (blockIdx.x & 7) * 2048 + threadIdx.x * 8;
    const int k0  = (blockIdx.x >> 3) * 64;

    u32 tqA = 0, tqB = 0;
#pragma unroll
    for (int i = 0; i < 4; ++i) {
        tqA |= min(255u, g_dmin[tok + i]     + TQ_WIN) << (8 * i);
        tqB |= min(255u, g_dmin[tok + 4 + i] + TQ_WIN) << (8 * i);
    }

    const unsigned char* __restrict__ base = g_dq + tok + (size_t)k0 * NTOK;
#pragma unroll 8
    for (int ki = 0; ki < 64; ++ki) {
        uint2 v = *(const uint2*)(base + (size_t)ki * NTOK);
        u32 h0 = __vcmpleu4(v.x, tqA);
        u32 h1 = __vcmpleu4(v.y, tqB);
        if (h0 | h1) {
            const int k = k0 + ki;
#pragma unroll
            for (int q = 0; q < 4; ++q) {
                if ((h0 >> (8 * q)) & 1u) {
                    int t = tok + q;
                    int p = atomicAdd(&g_ccnt[t], 1);
                    if (p < CAND_CAP) g_cand[t * CAND_CAP + p] = k;
                }
                if ((h1 >> (8 * q)) & 1u) {
                    int t = tok + 4 + q;
                    int p = atomicAdd(&g_ccnt[t], 1);
                    if (p < CAND_CAP) g_cand[t * CAND_CAP + p] = k;
                }
            }
        }
    }
}

// ============================================================
// Kernel 4: EXACT rescore (bit-exact ascending-d chain, reference
// rounding, lex-min (d,k) = jnp.argmin). Warp per token; full-scan
// fallback on candidate overflow.
// ============================================================
__global__ __launch_bounds__(256) void rescore_kernel(const float* __restrict__ x,
                                                      const float* __restrict__ cb) {
    __shared__ float xs[8][DD];
    const int tid = threadIdx.x, w = tid >> 5, lane = tid & 31;
    const int n = blockIdx.x * 8 + w;
    const int b = n >> 10, hw = n & (HW - 1);
    const float* xp = x + (size_t)b * IMG + hw;
#pragma unroll
    for (int d = lane; d < DD; d += 32) xs[w][d] = xp[(size_t)d * HW];
    __syncwarp();

    const int cnt = g_ccnt[n];
    const float xn = g_xnorm[n];
    float bv = 3.4e38f;
    int   bi = 0x7FFFFFFF;

    if (cnt <= CAND_CAP) {
        for (int ci = lane; ci < cnt; ci += 32) {
            int k = g_cand[n * CAND_CAP + ci];
            const float* cp = cb + (size_t)k * DD;
            float m = 0.f;
#pragma unroll 8
            for (int d = 0; d < DD; ++d) m = fmaf(xs[w][d], cp[d], m);
            float dd = __fsub_rn(__fadd_rn(xn, g_cnorm[k]), 2.0f * m);
            if (dd < bv || (dd == bv && k < bi)) { bv = dd; bi = k; }
        }
    } else {   // overflow fallback: exact full scan
        for (int k = lane; k < KC; k += 32) {
            const float* cp = cb + (size_t)k * DD;
            float m = 0.f;
#pragma unroll 8
            for (int d = 0; d < DD; ++d) m = fmaf(xs[w][d], cp[d], m);
            float dd = __fsub_rn(__fadd_rn(xn, g_cnorm[k]), 2.0f * m);
            if (dd < bv || (dd == bv && k < bi)) { bv = dd; bi = k; }
        }
    }
#pragma unroll
    for (int off = 16; off; off >>= 1) {
        float ov = __shfl_xor_sync(0xffffffffu, bv, off);
        int   ob = __shfl_xor_sync(0xffffffffu, bi, off);
        if (ov < bv || (ov == bv && ob < bi)) { bv = ov; bi = ob; }
    }
    if (lane == 0) g_idx[n] = bi;
}

// ============================================================
// Kernel 5: gather quant, straight-through output, loss partial.
// ============================================================
__global__ __launch_bounds__(256) void epi_kernel(const float* __restrict__ x,
                                                  const float* __restrict__ cb,
                                                  float* __restrict__ out) {
    __shared__ int   sidx[64];
    __shared__ float swarp[8];
    const int tid  = threadIdx.x;
    const int tok0 = blockIdx.x * 64;
    const int bimg = tok0 >> 10;
    const int hw0  = tok0 & (HW - 1);

    if (tid < 64) sidx[tid] = g_idx[tok0 + tid];
    __syncthreads();

    const int m  = tid & 63;
    const int dh = tid >> 6;
    const size_t base = (size_t)bimg * IMG + hw0 + m;
    const long long crow = (long long)sidx[m] * DD;

    float lsum = 0.f;
#pragma unroll 8
    for (int d0 = 0; d0 < DD; d0 += 4) {
        int d = d0 + dh;
        float q  = cb[crow + d];
        size_t off = base + (size_t)d * HW;
        float xv = x[off];
        float t  = __fsub_rn(q, xv);
        out[off] = __fadd_rn(xv, t);
        lsum = fmaf(t, t, lsum);
    }
#pragma unroll
    for (int off = 16; off; off >>= 1) lsum += __shfl_xor_sync(0xffffffffu, lsum, off);
    if ((tid & 31) == 0) swarp[tid >> 5] = lsum;
    __syncthreads();
    if (tid == 0) {
        float s = 0.f;
        for (int wq = 0; wq < 8; ++wq) s += swarp[wq];
        g_partial[blockIdx.x] = s;
    }
    if (tid < 64) out[OUT_ENC + tok0 + tid] = (float)sidx[tid];
}

// ============================================================
// Kernel 6: finalize loss
// ============================================================
__global__ __launch_bounds__(256) void fin_kernel(float* __restrict__ out) {
    __shared__ float sw[8];
    int tid = threadIdx.x;
    float s = g_partial[tid];
#pragma unroll
    for (int off = 16; off; off >>= 1) s += __shfl_xor_sync(0xffffffffu, s, off);
    if ((tid & 31) == 0) sw[tid >> 5] = s;
    __syncthreads();
    if (tid == 0) {
        float tot = 0.f;
        for (int wq = 0; wq < 8; ++wq) tot += sw[wq];
        float mse = tot / 4194304.0f;
        out[OUT_LOSS] = __fadd_rn(mse, __fmul_rn(0.25f, mse));
    }
}

// ============================================================
extern "C" void kernel_launch(void* const* d_in, const int* in_sizes, int n_in,
                              void* d_out, int out_size) {
    const float* x  = (const float*)d_in[0];   // [16,256,32,32] fp32
    const float* cb = (const float*)d_in[1];   // [8192,256] fp32
    float* out = (float*)d_out;

    cudaFuncSetAttribute(gemm_kernel,
                         cudaFuncAttributeMaxDynamicSharedMemorySize, GEMM_SMEM);

    pre_kernel<<<3168, 256>>>(x, cb);
    gemm_kernel<<<4096, 512, GEMM_SMEM>>>();
    collect_kernel<<<1024, 256>>>();
    rescore_kernel<<<NTOK / 8, 256>>>(x, cb);
    epi_kernel<<<256, 256>>>(x, cb, out);
    fin_kernel<<<1, 256>>>(out);
}

// round 16
// speedup vs baseline: 8.2955x; 8.2955x over previous
#include <cuda_runtime.h>
#include <cuda_bf16.h>

// Problem constants
#define NTOK 16384      // B*H*W
#define KC   8192
#define DD   256
#define IMG  262144     // C*H*W
#define HW   1024

#define OUT_LOSS 4194304
#define OUT_ENC  4194305

// GEMM tiling: M = codes, N = tokens (round-12 validated)
#define CTM 128
#define CTN 256
#define CK  32
#define NCH (DD / CK)   // 8
#define NSTG 4
#define A_STG 8192
#define B_STG 16384
#define B_BASE (NSTG * A_STG)                 // 32768
#define GEMM_SMEM (B_BASE + NSTG * B_STG)     // 98304

#define EPS_WIN  1.0e-3f
#define CAND_CAP 64

typedef unsigned int u32;

// -------- scratch (device globals; no allocation allowed) --------
__device__ float g_cnorm[KC];
__device__ float g_xnorm[NTOK];
__device__ int   g_idx[NTOK];
__device__ float g_partial[256];
__device__ u32   g_dmin[NTOK];
__device__ int   g_ccnt[NTOK];
__device__ int   g_cand[NTOK * CAND_CAP];
__device__ __align__(16) __nv_bfloat16 g_xb[NTOK * DD];     // x [b][d][hw] bf16
__device__ __align__(16) __nv_bfloat16 g_cbb[KC * DD];      // [code][d] bf16
__device__ __align__(16) __nv_bfloat16 g_dtil[134217728];   // [code][token] 256MB

// -------- helpers --------
__device__ __forceinline__ u32 smem_u32(const void* p) {
    u32 a;
    asm("{ .reg .u64 t; cvta.to.shared.u64 t, %1; cvt.u32.u64 %0, t; }" : "=r"(a) : "l"(p));
    return a;
}
__device__ __forceinline__ void cpa(u32 dst, const void* src) {
    asm volatile("cp.async.cg.shared.global [%0], [%1], 16;" :: "r"(dst), "l"(src) : "memory");
}
#define CPC() asm volatile("cp.async.commit_group;" ::: "memory")
#define CPW(n) asm volatile("cp.async.wait_group %0;" :: "n"(n) : "memory")
__device__ __forceinline__ void ldsm4(u32& r0, u32& r1, u32& r2, u32& r3, u32 a) {
    asm volatile("ldmatrix.sync.aligned.m8n8.x4.shared.b16 {%0,%1,%2,%3}, [%4];"
                 : "=r"(r0), "=r"(r1), "=r"(r2), "=r"(r3) : "r"(a));
}
__device__ __forceinline__ void ldsm4t(u32& r0, u32& r1, u32& r2, u32& r3, u32 a) {
    asm volatile("ldmatrix.sync.aligned.m8n8.x4.trans.shared.b16 {%0,%1,%2,%3}, [%4];"
                 : "=r"(r0), "=r"(r1), "=r"(r2), "=r"(r3) : "r"(a));
}
__device__ __forceinline__ void mma16816(float* c, const u32* a, u32 b0, u32 b1) {
    asm volatile("mma.sync.aligned.m16n8k16.row.col.f32.bf16.bf16.f32 "
                 "{%0,%1,%2,%3}, {%4,%5,%6,%7}, {%8,%9}, {%0,%1,%2,%3};"
                 : "+f"(c[0]), "+f"(c[1]), "+f"(c[2]), "+f"(c[3])
                 : "r"(a[0]), "r"(a[1]), "r"(a[2]), "r"(a[3]), "r"(b0), "r"(b1));
}
__device__ __forceinline__ u32 pack_bf(float lo, float hi) {  // lo -> bits[0:16)
    u32 r;
    asm("cvt.rn.bf16x2.f32 %0, %1, %2;" : "=r"(r) : "f"(hi), "f"(lo));
    return r;
}
__device__ __forceinline__ u32 min2bf(u32 a, u32 b) {
    u32 r;
    asm("min.bf16x2 %0, %1, %2;" : "=r"(r) : "r"(a), "r"(b));
    return r;
}
__device__ __forceinline__ float bf_lo(u32 w) { return __uint_as_float(w << 16); }
__device__ __forceinline__ float bf_hi(u32 w) { return __uint_as_float(w & 0xFFFF0000u); }
__device__ __forceinline__ u32 fkey(float f) {   // orderable-uint encode
    u32 b = __float_as_uint(f);
    return (b & 0x80000000u) ? ~b : (b | 0x80000000u);
}

// ============================================================
// Kernel 1: FUSED norms (strict sequential fp32 chains, bit-exact)
// + bf16 conversion. Blocks [0,96): norms+init; [96,3168): convert.
// (This fusion ran correct in round 15; orthogonal to the rejected
// u8 experiment.)
// ============================================================
__global__ __launch_bounds__(256) void pre_kernel(const float* __restrict__ x,
                                                  const float* __restrict__ cb) {
    int blk = blockIdx.x;
    if (blk < 32) {
        int k = blk * 256 + threadIdx.x;
        const float* p = cb + (size_t)k * DD;
        float s = 0.f;
#pragma unroll 8
        for (int d = 0; d < DD; ++d) { float v = p[d]; s = __fadd_rn(s, __fmul_rn(v, v)); }
        g_cnorm[k] = s;
    } else if (blk < 96) {
        int n  = (blk - 32) * 256 + threadIdx.x;
        int b  = n >> 10, hw = n & (HW - 1);
        const float* p = x + (size_t)b * IMG + hw;
        float s = 0.f;
#pragma unroll 8
        for (int d = 0; d < DD; ++d) { float v = p[(size_t)d * HW]; s = __fadd_rn(s, __fmul_rn(v, v)); }
        g_xnorm[n] = s;
        g_dmin[n]  = 0xFFFFFFFFu;
        g_ccnt[n]  = 0;
    } else {
        size_t i = ((size_t)(blk - 96) * 256 + threadIdx.x) * 8;
        const float4* s;
        __nv_bfloat16* d;
        if (i < (size_t)NTOK * DD) { s = (const float4*)(x + i);              d = g_xb + i; }
        else { size_t j = i - (size_t)NTOK * DD; s = (const float4*)(cb + j); d = g_cbb + j; }
        float4 v0 = s[0], v1 = s[1];
        uint4 w;
        w.x = pack_bf(v0.x, v0.y); w.y = pack_bf(v0.z, v0.w);
        w.z = pack_bf(v1.x, v1.y); w.w = pack_bf(v1.z, v1.w);
        *(uint4*)d = w;
    }
}

// ============================================================
// Kernel 2: HMMA bf16 prescreen GEMM — ROUND-12 CHAMPION, unchanged.
// 4-stage cp.async, empty-commit tail fix, bf16 dtil epilogue.
// ============================================================
__global__ __launch_bounds__(512, 1) void gemm_kernel() {
    extern __shared__ __align__(16) char sm[];
    const u32 smU = smem_u32(sm);
    const int tid  = threadIdx.x;
    const int lane = tid & 31;
    const int wid  = tid >> 5;
    const int wm   = wid & 3;      // code group (32 codes)
    const int wn   = wid >> 2;     // token group (64 tokens)

    const int code0 = (blockIdx.x & 63) * CTM;
    const int tok0  = (blockIdx.x >> 6) * CTN;
    const int bimg  = tok0 >> 10;
    const int hw0   = tok0 & (HW - 1);

    const int arow = tid >> 2, ac = tid & 3;
    const __nv_bfloat16* aG = g_cbb + (size_t)(code0 + arow) * DD + ac * 8;
    const u32 aOff = (u32)arow * 64u + (u32)((ac ^ ((arow >> 1) & 3))) * 16u;
    const int bd = tid >> 4, bc = tid & 15;
    const __nv_bfloat16* bG = g_xb + (size_t)bimg * IMG + hw0 + (size_t)bd * HW + bc * 8;
    const u32 bOff0 = (u32)bd * 512u + (u32)((bc        ^ (bd & 7))) * 16u;
    const u32 bOff1 = (u32)bd * 512u + (u32)(((bc + 16) ^ (bd & 7))) * 16u;

    float acc[2][8][4];
#pragma unroll
    for (int mi = 0; mi < 2; ++mi)
#pragma unroll
        for (int nt = 0; nt < 8; ++nt)
#pragma unroll
            for (int q = 0; q < 4; ++q) acc[mi][nt][q] = 0.f;

#define LOAD_CHUNK(ch) do {                                                   \
        const u32 _st = (u32)((ch) & (NSTG - 1));                             \
        cpa(smU + _st * A_STG + aOff, aG + (ch) * CK);                        \
        cpa(smU + B_BASE + _st * B_STG + bOff0, bG + (size_t)(ch) * CK * HW); \
        cpa(smU + B_BASE + _st * B_STG + bOff1,                               \
            bG + (size_t)(ch) * CK * HW + 128);                               \
        CPC();                                                                \
    } while (0)

    LOAD_CHUNK(0);
    LOAD_CHUNK(1);
    LOAD_CHUNK(2);

    const int sa = ((lane & 15) >> 1) & 3;
    const int sb = lane & 7;
    const u32 aFragBase = smU + (u32)(wm * 32 + (lane & 15)) * 64u;
    const u32 bFragBase = smU + B_BASE + (u32)(lane & 15) * 512u;

    for (int ch = 0; ch < NCH; ++ch) {
        CPW(2);                    // per-iter commits: chunks 0..ch landed
        __syncthreads();           // stage (ch-1)&3 readers all done
        if (ch + 3 < NCH) LOAD_CHUNK(ch + 3);
        else              CPC();   // EMPTY group keeps wait_group advancing

        const u32 st = (u32)(ch & (NSTG - 1));
#pragma unroll
        for (int kk = 0; kk < 2; ++kk) {
            u32 a0[4], a1[4];
            const u32 aTop = (u32)(((kk * 2 + (lane >> 4)) ^ sa)) * 16u + st * A_STG;
            ldsm4(a0[0], a0[1], a0[2], a0[3], aFragBase + aTop);
            ldsm4(a1[0], a1[1], a1[2], a1[3], aFragBase + 1024u + aTop);
            const u32 bRow = st * B_STG + (u32)(kk * 16) * 512u;
#pragma unroll
            for (int np = 0; np < 4; ++np) {
                u32 b0, b1, b2, b3;
                const u32 c = (u32)(((wn * 8 + np * 2 + (lane >> 4)) ^ sb)) * 16u;
                ldsm4t(b0, b1, b2, b3, bFragBase + bRow + c);
                mma16816(acc[0][2 * np],     a0, b0, b1);
                mma16816(acc[0][2 * np + 1], a0, b2, b3);
                mma16816(acc[1][2 * np],     a1, b0, b1);
                mma16816(acc[1][2 * np + 1], a1, b2, b3);
            }
        }
    }
#undef LOAD_CHUNK

    // ---- epilogue: bf16 dtil store + per-token min (round-12 exact) ----
    float tmn[8][2];
#pragma unroll
    for (int nt = 0; nt < 8; ++nt) { tmn[nt][0] = 3.4e38f; tmn[nt][1] = 3.4e38f; }
#pragma unroll
    for (int mi = 0; mi < 2; ++mi)
#pragma unroll
        for (int h = 0; h < 2; ++h) {
            const int code = code0 + wm * 32 + mi * 16 + (lane >> 2) + h * 8;
            const float cn = g_cnorm[code];
            __nv_bfloat16* dst = g_dtil + (size_t)code * NTOK + tok0 + wn * 64 + 2 * (lane & 3);
#pragma unroll
            for (int nt = 0; nt < 8; ++nt) {
                float dv0 = fmaf(-2.f, acc[mi][nt][h * 2 + 0], cn);
                float dv1 = fmaf(-2.f, acc[mi][nt][h * 2 + 1], cn);
                u32 w = pack_bf(dv0, dv1);
                *(u32*)(dst + (size_t)nt * 8) = w;
                tmn[nt][0] = fminf(tmn[nt][0], bf_lo(w));
                tmn[nt][1] = fminf(tmn[nt][1], bf_hi(w));
            }
        }
#pragma unroll
    for (int nt = 0; nt < 8; ++nt)
#pragma unroll
        for (int off = 16; off >= 4; off >>= 1) {
            tmn[nt][0] = fminf(tmn[nt][0], __shfl_xor_sync(0xffffffffu, tmn[nt][0], off));
            tmn[nt][1] = fminf(tmn[nt][1], __shfl_xor_sync(0xffffffffu, tmn[nt][1], off));
        }
    if (lane < 4) {
#pragma unroll
        for (int nt = 0; nt < 8; ++nt) {
            int t = tok0 + wn * 64 + nt * 8 + 2 * lane;
            atomicMin(&g_dmin[t],     fkey(tmn[nt][0]));
            atomicMin(&g_dmin[t + 1], fkey(tmn[nt][1]));
        }
    }
}

// ============================================================
// Kernel 3: candidate collection — COALESCED uint4 row scan
// (round-12 exact; measured ~60us).
// ============================================================
__global__ __launch_bounds__(256) void collect_kernel() {
    const int tok = (blockIdx.x & 7) * 2048 + threadIdx.x * 8;
    const int k0  = (blockIdx.x >> 3) * 64;

    float thr[8];
#pragma unroll
    for (int i = 0; i < 8; ++i) {
        u32 key = g_dmin[tok + i];
        u32 mb  = (key & 0x80000000u) ? (key ^ 0x80000000u) : ~key;
        thr[i] = __uint_as_float(mb) + EPS_WIN;
    }
    const float te = fmaxf(fmaxf(thr[0], thr[2]), fmaxf(thr[4], thr[6]));
    const float to = fmaxf(fmaxf(thr[1], thr[3]), fmaxf(thr[5], thr[7]));

    const uint4* __restrict__ base =
        (const uint4*)(g_dtil + tok) + (size_t)k0 * (NTOK / 8);
#pragma unroll 8
    for (int ki = 0; ki < 64; ++ki) {
        uint4 v = base[(size_t)ki * (NTOK / 8)];
        u32 m = min2bf(min2bf(v.x, v.y), min2bf(v.z, v.w));
        if (bf_lo(m) <= te || bf_hi(m) <= to) {          // rare fast-path trigger
            const int k = k0 + ki;
            const u32* wp = (const u32*)&v;
#pragma unroll
            for (int q = 0; q < 4; ++q) {
                u32 w = wp[q];
                if (bf_lo(w) <= thr[2 * q]) {
                    int t = tok + 2 * q;
                    int p = atomicAdd(&g_ccnt[t], 1);
                    if (p < CAND_CAP) g_cand[t * CAND_CAP + p] = k;
                }
                if (bf_hi(w) <= thr[2 * q + 1]) {
                    int t = tok + 2 * q + 1;
                    int p = atomicAdd(&g_ccnt[t], 1);
                    if (p < CAND_CAP) g_cand[t * CAND_CAP + p] = k;
                }
            }
        }
    }
}

// ============================================================
// Kernel 4: EXACT rescore (bit-exact ascending-d chain, reference
// rounding, lex-min (d,k) = jnp.argmin). Warp per token; full-scan
// fallback on candidate overflow.
// ============================================================
__global__ __launch_bounds__(256) void rescore_kernel(const float* __restrict__ x,
                                                      const float* __restrict__ cb) {
    __shared__ float xs[8][DD];
    const int tid = threadIdx.x, w = tid >> 5, lane = tid & 31;
    const int n = blockIdx.x * 8 + w;
    const int b = n >> 10, hw = n & (HW - 1);
    const float* xp = x + (size_t)b * IMG + hw;
#pragma unroll
    for (int d = lane; d < DD; d += 32) xs[w][d] = xp[(size_t)d * HW];
    __syncwarp();

    const int cnt = g_ccnt[n];
    const float xn = g_xnorm[n];
    float bv = 3.4e38f;
    int   bi = 0x7FFFFFFF;

    if (cnt <= CAND_CAP) {
        for (int ci = lane; ci < cnt; ci += 32) {
            int k = g_cand[n * CAND_CAP + ci];
            const float* cp = cb + (size_t)k * DD;
            float m = 0.f;
#pragma unroll 8
            for (int d = 0; d < DD; ++d) m = fmaf(xs[w][d], cp[d], m);
            float dd = __fsub_rn(__fadd_rn(xn, g_cnorm[k]), 2.0f * m);
            if (dd < bv || (dd == bv && k < bi)) { bv = dd; bi = k; }
        }
    } else {   // overflow fallback: exact full scan
        for (int k = lane; k < KC; k += 32) {
            const float* cp = cb + (size_t)k * DD;
            float m = 0.f;
#pragma unroll 8
            for (int d = 0; d < DD; ++d) m = fmaf(xs[w][d], cp[d], m);
            float dd = __fsub_rn(__fadd_rn(xn, g_cnorm[k]), 2.0f * m);
            if (dd < bv || (dd == bv && k < bi)) { bv = dd; bi = k; }
        }
    }
#pragma unroll
    for (int off = 16; off; off >>= 1) {
        float ov = __shfl_xor_sync(0xffffffffu, bv, off);
        int   ob = __shfl_xor_sync(0xffffffffu, bi, off);
        if (ov < bv || (ov == bv && ob < bi)) { bv = ov; bi = ob; }
    }
    if (lane == 0) g_idx[n] = bi;
}

// ============================================================
// Kernel 5: gather quant, straight-through output, loss partial.
// ============================================================
__global__ __launch_bounds__(256) void epi_kernel(const float* __restrict__ x,
                                                  const float* __restrict__ cb,
                                                  float* __restrict__ out) {
    __shared__ int   sidx[64];
    __shared__ float swarp[8];
    const int tid  = threadIdx.x;
    const int tok0 = blockIdx.x * 64;
    const int bimg = tok0 >> 10;
    const int hw0  = tok0 & (HW - 1);

    if (tid < 64) sidx[tid] = g_idx[tok0 + tid];
    __syncthreads();

    const int m  = tid & 63;
    const int dh = tid >> 6;
    const size_t base = (size_t)bimg * IMG + hw0 + m;
    const long long crow = (long long)sidx[m] * DD;

    float lsum = 0.f;
#pragma unroll 8
    for (int d0 = 0; d0 < DD; d0 += 4) {
        int d = d0 + dh;
        float q  = cb[crow + d];
        size_t off = base + (size_t)d * HW;
        float xv = x[off];
        float t  = __fsub_rn(q, xv);
        out[off] = __fadd_rn(xv, t);
        lsum = fmaf(t, t, lsum);
    }
#pragma unroll
    for (int off = 16; off; off >>= 1) lsum += __shfl_xor_sync(0xffffffffu, lsum, off);
    if ((tid & 31) == 0) swarp[tid >> 5] = lsum;
    __syncthreads();
    if (tid == 0) {
        float s = 0.f;
        for (int wq = 0; wq < 8; ++wq) s += swarp[wq];
        g_partial[blockIdx.x] = s;
    }
    if (tid < 64) out[OUT_ENC + tok0 + tid] = (float)sidx[tid];
}

// ============================================================
// Kernel 6: finalize loss
// ============================================================
__global__ __launch_bounds__(256) void fin_kernel(float* __restrict__ out) {
    __shared__ float sw[8];
    int tid = threadIdx.x;
    float s = g_partial[tid];
#pragma unroll
    for (int off = 16; off; off >>= 1) s += __shfl_xor_sync(0xffffffffu, s, off);
    if ((tid & 31) == 0) sw[tid >> 5] = s;
    __syncthreads();
    if (tid == 0) {
        float tot = 0.f;
        for (int wq = 0; wq < 8; ++wq) tot += sw[wq];
        float mse = tot / 4194304.0f;
        out[OUT_LOSS] = __fadd_rn(mse, __fmul_rn(0.25f, mse));
    }
}

// ============================================================
extern "C" void kernel_launch(void* const* d_in, const int* in_sizes, int n_in,
                              void* d_out, int out_size) {
    const float* x  = (const float*)d_in[0];   // [16,256,32,32] fp32
    const float* cb = (const float*)d_in[1];   // [8192,256] fp32
    float* out = (float*)d_out;

    cudaFuncSetAttribute(gemm_kernel,
                         cudaFuncAttributeMaxDynamicSharedMemorySize, GEMM_SMEM);

    pre_kernel<<<3168, 256>>>(x, cb);
    gemm_kernel<<<4096, 512, GEMM_SMEM>>>();
    collect_kernel<<<1024, 256>>>();
    rescore_kernel<<<NTOK / 8, 256>>>(x, cb);
    epi_kernel<<<256, 256>>>(x, cb, out);
    fin_kernel<<<1, 256>>>(out);
}

// round 17
// speedup vs baseline: 9.4554x; 1.1398x over previous
#include <cuda_runtime.h>
#include <cuda_bf16.h>

// Problem constants
#define NTOK 16384      // B*H*W
#define KC   8192
#define DD   256
#define IMG  262144     // C*H*W
#define HW   1024

#define OUT_LOSS 4194304
#define OUT_ENC  4194305

// GEMM tiling: M = codes, N = tokens (round-12 validated)
#define CTM 128
#define CTN 256
#define CK  32
#define NCH (DD / CK)   // 8
#define NSTG 4
#define A_STG 8192
#define B_STG 16384
#define B_BASE (NSTG * A_STG)                 // 32768
#define GEMM_SMEM (B_BASE + NSTG * B_STG)     // 98304

#define EPS_WIN  1.0e-3f
#define CAND_CAP 64

typedef unsigned int u32;

// -------- scratch (device globals; no allocation allowed) --------
__device__ float g_cnorm[KC];
__device__ float g_xnorm[NTOK];
__device__ int   g_idx[NTOK];
__device__ float g_partial[256];
__device__ u32   g_dmin[NTOK];
__device__ int   g_ccnt[NTOK];
__device__ int   g_cand[NTOK * CAND_CAP];
__device__ __align__(16) __nv_bfloat16 g_xb[NTOK * DD];     // x [b][d][hw] bf16
__device__ __align__(16) __nv_bfloat16 g_cbb[KC * DD];      // [code][d] bf16
__device__ __align__(16) __nv_bfloat16 g_dtil[134217728];   // [code][token] 256MB

// -------- helpers --------
__device__ __forceinline__ u32 smem_u32(const void* p) {
    u32 a;
    asm("{ .reg .u64 t; cvta.to.shared.u64 t, %1; cvt.u32.u64 %0, t; }" : "=r"(a) : "l"(p));
    return a;
}
__device__ __forceinline__ void cpa(u32 dst, const void* src) {
    asm volatile("cp.async.cg.shared.global [%0], [%1], 16;" :: "r"(dst), "l"(src) : "memory");
}
#define CPC() asm volatile("cp.async.commit_group;" ::: "memory")
#define CPW(n) asm volatile("cp.async.wait_group %0;" :: "n"(n) : "memory")
__device__ __forceinline__ void ldsm4(u32& r0, u32& r1, u32& r2, u32& r3, u32 a) {
    asm volatile("ldmatrix.sync.aligned.m8n8.x4.shared.b16 {%0,%1,%2,%3}, [%4];"
                 : "=r"(r0), "=r"(r1), "=r"(r2), "=r"(r3) : "r"(a));
}
__device__ __forceinline__ void ldsm4t(u32& r0, u32& r1, u32& r2, u32& r3, u32 a) {
    asm volatile("ldmatrix.sync.aligned.m8n8.x4.trans.shared.b16 {%0,%1,%2,%3}, [%4];"
                 : "=r"(r0), "=r"(r1), "=r"(r2), "=r"(r3) : "r"(a));
}
__device__ __forceinline__ void mma16816(float* c, const u32* a, u32 b0, u32 b1) {
    asm volatile("mma.sync.aligned.m16n8k16.row.col.f32.bf16.bf16.f32 "
                 "{%0,%1,%2,%3}, {%4,%5,%6,%7}, {%8,%9}, {%0,%1,%2,%3};"
                 : "+f"(c[0]), "+f"(c[1]), "+f"(c[2]), "+f"(c[3])
                 : "r"(a[0]), "r"(a[1]), "r"(a[2]), "r"(a[3]), "r"(b0), "r"(b1));
}
__device__ __forceinline__ u32 pack_bf(float lo, float hi) {  // lo -> bits[0:16)
    u32 r;
    asm("cvt.rn.bf16x2.f32 %0, %1, %2;" : "=r"(r) : "f"(hi), "f"(lo));
    return r;
}
__device__ __forceinline__ u32 min2bf(u32 a, u32 b) {
    u32 r;
    asm("min.bf16x2 %0, %1, %2;" : "=r"(r) : "r"(a), "r"(b));
    return r;
}
__device__ __forceinline__ float bf_lo(u32 w) { return __uint_as_float(w << 16); }
__device__ __forceinline__ float bf_hi(u32 w) { return __uint_as_float(w & 0xFFFF0000u); }
__device__ __forceinline__ u32 fkey(float f) {   // orderable-uint encode
    u32 b = __float_as_uint(f);
    return (b & 0x80000000u) ? ~b : (b | 0x80000000u);
}

// exact sequential dot: SAME ascending-d fmaf chain, vectorized loads.
// consumes x,y,z,w in order => identical rounding to the scalar loop.
__device__ __forceinline__ float dot_chain(const float4* __restrict__ xs4,
                                           const float4* __restrict__ cp4) {
    float m = 0.f;
#pragma unroll 8
    for (int i = 0; i < DD / 4; ++i) {
        float4 xv = xs4[i];
        float4 cv = cp4[i];
        m = fmaf(xv.x, cv.x, m);
        m = fmaf(xv.y, cv.y, m);
        m = fmaf(xv.z, cv.z, m);
        m = fmaf(xv.w, cv.w, m);
    }
    return m;
}

// ============================================================
// Kernel 1: FUSED norms (strict sequential fp32 chains, bit-exact)
// + bf16 conversion. Blocks [0,96): norms+init; [96,3168): convert.
// ============================================================
__global__ __launch_bounds__(256) void pre_kernel(const float* __restrict__ x,
                                                  const float* __restrict__ cb) {
    int blk = blockIdx.x;
    if (blk < 32) {
        int k = blk * 256 + threadIdx.x;
        const float* p = cb + (size_t)k * DD;
        float s = 0.f;
#pragma unroll 8
        for (int d = 0; d < DD; ++d) { float v = p[d]; s = __fadd_rn(s, __fmul_rn(v, v)); }
        g_cnorm[k] = s;
    } else if (blk < 96) {
        int n  = (blk - 32) * 256 + threadIdx.x;
        int b  = n >> 10, hw = n & (HW - 1);
        const float* p = x + (size_t)b * IMG + hw;
        float s = 0.f;
#pragma unroll 8
        for (int d = 0; d < DD; ++d) { float v = p[(size_t)d * HW]; s = __fadd_rn(s, __fmul_rn(v, v)); }
        g_xnorm[n] = s;
        g_dmin[n]  = 0xFFFFFFFFu;
        g_ccnt[n]  = 0;
    } else {
        size_t i = ((size_t)(blk - 96) * 256 + threadIdx.x) * 8;
        const float4* s;
        __nv_bfloat16* d;
        if (i < (size_t)NTOK * DD) { s = (const float4*)(x + i);              d = g_xb + i; }
        else { size_t j = i - (size_t)NTOK * DD; s = (const float4*)(cb + j); d = g_cbb + j; }
        float4 v0 = s[0], v1 = s[1];
        uint4 w;
        w.x = pack_bf(v0.x, v0.y); w.y = pack_bf(v0.z, v0.w);
        w.z = pack_bf(v1.x, v1.y); w.w = pack_bf(v1.z, v1.w);
        *(uint4*)d = w;
    }
}

// ============================================================
// Kernel 2: HMMA bf16 prescreen GEMM — ROUND-12 CHAMPION, unchanged.
// ============================================================
__global__ __launch_bounds__(512, 1) void gemm_kernel() {
    extern __shared__ __align__(16) char sm[];
    const u32 smU = smem_u32(sm);
    const int tid  = threadIdx.x;
    const int lane = tid & 31;
    const int wid  = tid >> 5;
    const int wm   = wid & 3;
    const int wn   = wid >> 2;

    const int code0 = (blockIdx.x & 63) * CTM;
    const int tok0  = (blockIdx.x >> 6) * CTN;
    const int bimg  = tok0 >> 10;
    const int hw0   = tok0 & (HW - 1);

    const int arow = tid >> 2, ac = tid & 3;
    const __nv_bfloat16* aG = g_cbb + (size_t)(code0 + arow) * DD + ac * 8;
    const u32 aOff = (u32)arow * 64u + (u32)((ac ^ ((arow >> 1) & 3))) * 16u;
    const int bd = tid >> 4, bc = tid & 15;
    const __nv_bfloat16* bG = g_xb + (size_t)bimg * IMG + hw0 + (size_t)bd * HW + bc * 8;
    const u32 bOff0 = (u32)bd * 512u + (u32)((bc        ^ (bd & 7))) * 16u;
    const u32 bOff1 = (u32)bd * 512u + (u32)(((bc + 16) ^ (bd & 7))) * 16u;

    float acc[2][8][4];
#pragma unroll
    for (int mi = 0; mi < 2; ++mi)
#pragma unroll
        for (int nt = 0; nt < 8; ++nt)
#pragma unroll
            for (int q = 0; q < 4; ++q) acc[mi][nt][q] = 0.f;

#define LOAD_CHUNK(ch) do {                                                   \
        const u32 _st = (u32)((ch) & (NSTG - 1));                             \
        cpa(smU + _st * A_STG + aOff, aG + (ch) * CK);                        \
        cpa(smU + B_BASE + _st * B_STG + bOff0, bG + (size_t)(ch) * CK * HW); \
        cpa(smU + B_BASE + _st * B_STG + bOff1,                               \
            bG + (size_t)(ch) * CK * HW + 128);                               \
        CPC();                                                                \
    } while (0)

    LOAD_CHUNK(0);
    LOAD_CHUNK(1);
    LOAD_CHUNK(2);

    const int sa = ((lane & 15) >> 1) & 3;
    const int sb = lane & 7;
    const u32 aFragBase = smU + (u32)(wm * 32 + (lane & 15)) * 64u;
    const u32 bFragBase = smU + B_BASE + (u32)(lane & 15) * 512u;

    for (int ch = 0; ch < NCH; ++ch) {
        CPW(2);
        __syncthreads();
        if (ch + 3 < NCH) LOAD_CHUNK(ch + 3);
        else              CPC();   // EMPTY group keeps wait_group advancing

        const u32 st = (u32)(ch & (NSTG - 1));
#pragma unroll
        for (int kk = 0; kk < 2; ++kk) {
            u32 a0[4], a1[4];
            const u32 aTop = (u32)(((kk * 2 + (lane >> 4)) ^ sa)) * 16u + st * A_STG;
            ldsm4(a0[0], a0[1], a0[2], a0[3], aFragBase + aTop);
            ldsm4(a1[0], a1[1], a1[2], a1[3], aFragBase + 1024u + aTop);
            const u32 bRow = st * B_STG + (u32)(kk * 16) * 512u;
#pragma unroll
            for (int np = 0; np < 4; ++np) {
                u32 b0, b1, b2, b3;
                const u32 c = (u32)(((wn * 8 + np * 2 + (lane >> 4)) ^ sb)) * 16u;
                ldsm4t(b0, b1, b2, b3, bFragBase + bRow + c);
                mma16816(acc[0][2 * np],     a0, b0, b1);
                mma16816(acc[0][2 * np + 1], a0, b2, b3);
                mma16816(acc[1][2 * np],     a1, b0, b1);
                mma16816(acc[1][2 * np + 1], a1, b2, b3);
            }
        }
    }
#undef LOAD_CHUNK

    // ---- epilogue: bf16 dtil store + per-token min ----
    float tmn[8][2];
#pragma unroll
    for (int nt = 0; nt < 8; ++nt) { tmn[nt][0] = 3.4e38f; tmn[nt][1] = 3.4e38f; }
#pragma unroll
    for (int mi = 0; mi < 2; ++mi)
#pragma unroll
        for (int h = 0; h < 2; ++h) {
            const int code = code0 + wm * 32 + mi * 16 + (lane >> 2) + h * 8;
            const float cn = g_cnorm[code];
            __nv_bfloat16* dst = g_dtil + (size_t)code * NTOK + tok0 + wn * 64 + 2 * (lane & 3);
#pragma unroll
            for (int nt = 0; nt < 8; ++nt) {
                float dv0 = fmaf(-2.f, acc[mi][nt][h * 2 + 0], cn);
                float dv1 = fmaf(-2.f, acc[mi][nt][h * 2 + 1], cn);
                u32 w = pack_bf(dv0, dv1);
                *(u32*)(dst + (size_t)nt * 8) = w;
                tmn[nt][0] = fminf(tmn[nt][0], bf_lo(w));
                tmn[nt][1] = fminf(tmn[nt][1], bf_hi(w));
            }
        }
#pragma unroll
    for (int nt = 0; nt < 8; ++nt)
#pragma unroll
        for (int off = 16; off >= 4; off >>= 1) {
            tmn[nt][0] = fminf(tmn[nt][0], __shfl_xor_sync(0xffffffffu, tmn[nt][0], off));
            tmn[nt][1] = fminf(tmn[nt][1], __shfl_xor_sync(0xffffffffu, tmn[nt][1], off));
        }
    if (lane < 4) {
#pragma unroll
        for (int nt = 0; nt < 8; ++nt) {
            int t = tok0 + wn * 64 + nt * 8 + 2 * lane;
            atomicMin(&g_dmin[t],     fkey(tmn[nt][0]));
            atomicMin(&g_dmin[t + 1], fkey(tmn[nt][1]));
        }
    }
}

// ============================================================
// Kernel 3: candidate collection — COALESCED uint4 row scan.
// ============================================================
__global__ __launch_bounds__(256) void collect_kernel() {
    const int tok = (blockIdx.x & 7) * 2048 + threadIdx.x * 8;
    const int k0  = (blockIdx.x >> 3) * 64;

    float thr[8];
#pragma unroll
    for (int i = 0; i < 8; ++i) {
        u32 key = g_dmin[tok + i];
        u32 mb  = (key & 0x80000000u) ? (key ^ 0x80000000u) : ~key;
        thr[i] = __uint_as_float(mb) + EPS_WIN;
    }
    const float te = fmaxf(fmaxf(thr[0], thr[2]), fmaxf(thr[4], thr[6]));
    const float to = fmaxf(fmaxf(thr[1], thr[3]), fmaxf(thr[5], thr[7]));

    const uint4* __restrict__ base =
        (const uint4*)(g_dtil + tok) + (size_t)k0 * (NTOK / 8);
#pragma unroll 8
    for (int ki = 0; ki < 64; ++ki) {
        uint4 v = base[(size_t)ki * (NTOK / 8)];
        u32 m = min2bf(min2bf(v.x, v.y), min2bf(v.z, v.w));
        if (bf_lo(m) <= te || bf_hi(m) <= to) {
            const int k = k0 + ki;
            const u32* wp = (const u32*)&v;
#pragma unroll
            for (int q = 0; q < 4; ++q) {
                u32 w = wp[q];
                if (bf_lo(w) <= thr[2 * q]) {
                    int t = tok + 2 * q;
                    int p = atomicAdd(&g_ccnt[t], 1);
                    if (p < CAND_CAP) g_cand[t * CAND_CAP + p] = k;
                }
                if (bf_hi(w) <= thr[2 * q + 1]) {
                    int t = tok + 2 * q + 1;
                    int p = atomicAdd(&g_ccnt[t], 1);
                    if (p < CAND_CAP) g_cand[t * CAND_CAP + p] = k;
                }
            }
        }
    }
}

// ============================================================
// Kernel 4: EXACT rescore — VECTORIZED loads (LDG.128 / LDS.128),
// identical ascending-d fmaf chain per candidate (bit-exact).
// Warp per token; full-scan fallback on candidate overflow.
// ============================================================
__global__ __launch_bounds__(256) void rescore_kernel(const float* __restrict__ x,
                                                      const float* __restrict__ cb) {
    __shared__ __align__(16) float xs[8][DD];
    const int tid = threadIdx.x, w = tid >> 5, lane = tid & 31;
    const int n = blockIdx.x * 8 + w;
    const int b = n >> 10, hw = n & (HW - 1);
    const float* xp = x + (size_t)b * IMG + hw;
#pragma unroll
    for (int d = lane; d < DD; d += 32) xs[w][d] = xp[(size_t)d * HW];
    __syncwarp();

    const float4* xs4 = (const float4*)xs[w];
    const int cnt = g_ccnt[n];
    const float xn = g_xnorm[n];
    float bv = 3.4e38f;
    int   bi = 0x7FFFFFFF;

    if (cnt <= CAND_CAP) {
        for (int ci = lane; ci < cnt; ci += 32) {
            int k = g_cand[n * CAND_CAP + ci];
            float m = dot_chain(xs4, (const float4*)(cb + (size_t)k * DD));
            float dd = __fsub_rn(__fadd_rn(xn, g_cnorm[k]), 2.0f * m);
            if (dd < bv || (dd == bv && k < bi)) { bv = dd; bi = k; }
        }
    } else {   // overflow fallback: exact full scan
        for (int k = lane; k < KC; k += 32) {
            float m = dot_chain(xs4, (const float4*)(cb + (size_t)k * DD));
            float dd = __fsub_rn(__fadd_rn(xn, g_cnorm[k]), 2.0f * m);
            if (dd < bv || (dd == bv && k < bi)) { bv = dd; bi = k; }
        }
    }
#pragma unroll
    for (int off = 16; off; off >>= 1) {
        float ov = __shfl_xor_sync(0xffffffffu, bv, off);
        int   ob = __shfl_xor_sync(0xffffffffu, bi, off);
        if (ov < bv || (ov == bv && ob < bi)) { bv = ov; bi = ob; }
    }
    if (lane == 0) g_idx[n] = bi;
}

// ============================================================
// Kernel 5: gather quant, straight-through output, loss partial.
// ============================================================
__global__ __launch_bounds__(256) void epi_kernel(const float* __restrict__ x,
                                                  const float* __restrict__ cb,
                                                  float* __restrict__ out) {
    __shared__ int   sidx[64];
    __shared__ float swarp[8];
    const int tid  = threadIdx.x;
    const int tok0 = blockIdx.x * 64;
    const int bimg = tok0 >> 10;
    const int hw0  = tok0 & (HW - 1);

    if (tid < 64) sidx[tid] = g_idx[tok0 + tid];
    __syncthreads();

    const int m  = tid & 63;
    const int dh = tid >> 6;
    const size_t base = (size_t)bimg * IMG + hw0 + m;
    const long long crow = (long long)sidx[m] * DD;

    float lsum = 0.f;
#pragma unroll 8
    for (int d0 = 0; d0 < DD; d0 += 4) {
        int d = d0 + dh;
        float q  = cb[crow + d];
        size_t off = base + (size_t)d * HW;
        float xv = x[off];
        float t  = __fsub_rn(q, xv);
        out[off] = __fadd_rn(xv, t);
        lsum = fmaf(t, t, lsum);
    }
#pragma unroll
    for (int off = 16; off; off >>= 1) lsum += __shfl_xor_sync(0xffffffffu, lsum, off);
    if ((tid & 31) == 0) swarp[tid >> 5] = lsum;
    __syncthreads();
    if (tid == 0) {
        float s = 0.f;
        for (int wq = 0; wq < 8; ++wq) s += swarp[wq];
        g_partial[blockIdx.x] = s;
    }
    if (tid < 64) out[OUT_ENC + tok0 + tid] = (float)sidx[tid];
}

// ============================================================
// Kernel 6: finalize loss
// ============================================================
__global__ __launch_bounds__(256) void fin_kernel(float* __restrict__ out) {
    __shared__ float sw[8];
    int tid = threadIdx.x;
    float s = g_partial[tid];
#pragma unroll
    for (int off = 16; off; off >>= 1) s += __shfl_xor_sync(0xffffffffu, s, off);
    if ((tid & 31) == 0) sw[tid >> 5] = s;
    __syncthreads();
    if (tid == 0) {
        float tot = 0.f;
        for (int wq = 0; wq < 8; ++wq) tot += sw[wq];
        float mse = tot / 4194304.0f;
        out[OUT_LOSS] = __fadd_rn(mse, __fmul_rn(0.25f, mse));
    }
}

// ============================================================
extern "C" void kernel_launch(void* const* d_in, const int* in_sizes, int n_in,
                              void* d_out, int out_size) {
    const float* x  = (const float*)d_in[0];   // [16,256,32,32] fp32
    const float* cb = (const float*)d_in[1];   // [8192,256] fp32
    float* out = (float*)d_out;

    cudaFuncSetAttribute(gemm_kernel,
                         cudaFuncAttributeMaxDynamicSharedMemorySize, GEMM_SMEM);

    pre_kernel<<<3168, 256>>>(x, cb);
    gemm_kernel<<<4096, 512, GEMM_SMEM>>>();
    collect_kernel<<<1024, 256>>>();
    rescore_kernel<<<NTOK / 8, 256>>>(x, cb);
    epi_kernel<<<256, 256>>>(x, cb, out);
    fin_kernel<<<1, 256>>>(out);
}